// round 8
// baseline (speedup 1.0000x reference)
#include <cuda_runtime.h>
#include <stdint.h>

#define BATCH    16
#define NBOX     4096
#define NCLS     80
#define MAX_DET  100
#define IOU_THR  0.5f
#define CONF_THR 0.5f
#define FULL     0xffffffffu
#define CHUNK    256
#define SUBS     4                  // 1024 threads / 256 candidates
#define NW       (CHUNK / 32)       // 8 mask words

// scratch: per-row sort keys  (score_bits << 32) | (0xFFFFFFFF - idx)
__device__ unsigned long long g_keys[BATCH * NBOX];

// guarded IoU>0.5 test: cheap compare with exact-divide fallback in a narrow
// borderline band (validated across passing rounds).
__device__ __forceinline__ bool iou_gt(float y1a, float x1a, float y2a, float x2a, float aa,
                                       float y1b, float x1b, float y2b, float x2b, float ab)
{
    float ih = fmaxf(0.0f, fminf(y2a, y2b) - fmaxf(y1a, y1b));
    float iw = fmaxf(0.0f, fminf(x2a, x2b) - fmaxf(x1a, x1b));
    float inter = ih * iw;
    float uni   = aa + ab - inter;
    float half  = 0.5f * uni;
    float diff  = inter - half;
    if (fabsf(diff) <= half * 1e-5f) {          // borderline: exact semantics
        float iou = (inter > 0.0f) ? inter / uni : 0.0f;
        return iou > IOU_THR;
    }
    return (diff > 0.0f) && (inter > 0.0f);
}

// ---------------------------------------------------------------------------
// Kernel 1: softmax(square(x*10)) per row, write cls_predictions, emit keys.
// ---------------------------------------------------------------------------
__global__ void __launch_bounds__(256)
softmax_key_kernel(const float* __restrict__ cls_in,
                   float* __restrict__ cls_out,
                   unsigned long long* __restrict__ keys)
{
    const int lane = threadIdx.x & 31;
    const int row  = blockIdx.x * (blockDim.x >> 5) + (threadIdx.x >> 5);
    if (row >= BATCH * NBOX) return;

    const float* in = cls_in + (size_t)row * NCLS;

    const bool has2 = lane < (NCLS - 64);
    float x0 = in[lane]      * 10.0f;
    float x1 = in[lane + 32] * 10.0f;
    float x2 = has2 ? in[lane + 64] * 10.0f : 0.0f;
    float a0 = x0 * x0, a1 = x1 * x1, a2 = x2 * x2;

    float amax = fmaxf(a0, a1);
    if (has2) amax = fmaxf(amax, a2);
    #pragma unroll
    for (int o = 16; o; o >>= 1)
        amax = fmaxf(amax, __shfl_xor_sync(FULL, amax, o));

    float e0 = expf(a0 - amax);
    float e1 = expf(a1 - amax);
    float e2 = has2 ? expf(a2 - amax) : 0.0f;

    float s = e0 + e1 + e2;
    #pragma unroll
    for (int o = 16; o; o >>= 1)
        s += __shfl_xor_sync(FULL, s, o);

    const float recip = 1.0f / s;
    float o0 = e0 * recip, o1 = e1 * recip, o2 = e2 * recip;

    float* out = cls_out + (size_t)row * NCLS;
    out[lane]      = o0;
    out[lane + 32] = o1;
    if (has2) out[lane + 64] = o2;

    float m = fmaxf(o0, o1);
    if (has2) m = fmaxf(m, o2);
    #pragma unroll
    for (int o = 16; o; o >>= 1)
        m = fmaxf(m, __shfl_xor_sync(FULL, m, o));

    if (lane == 0) {
        const unsigned n = (unsigned)(row & (NBOX - 1));
        keys[row] = ((unsigned long long)__float_as_uint(m) << 32)
                  | (unsigned long long)(0xffffffffu - n);
    }
}

// ---------------------------------------------------------------------------
// Kernel 2: sort + survivor-compacted bitmap NMS.
//   A1 (all threads) : candidates vs kept set -> ssup
//   compact          : survivor list (ballot prefix)
//   A2 (all threads) : suppression matrix over m survivors only
//   B  (thread 0)    : bit-scan resolve, work proportional to keeps
// Dynamic smem: float4 sbox[NBOX] | u64 sk[NBOX] | float sarea[NBOX]  (112KB)
// ---------------------------------------------------------------------------
__global__ void __launch_bounds__(1024, 1)
nms_kernel(const float* __restrict__ boxes,        // [B,N,4]
           const float* __restrict__ cls_soft,     // [B,N,C]
           const unsigned long long* __restrict__ keys,
           float* __restrict__ nms_box,            // [B,MAX_DET,4]
           float* __restrict__ nms_cls)            // [B,MAX_DET,C]
{
    extern __shared__ char dyn[];
    float4*             sbox  = (float4*)dyn;                       // 64KB
    unsigned long long* sk    = (unsigned long long*)(sbox + NBOX); // 32KB
    float*              sarea = (float*)(sk + NBOX);                // 16KB

    __shared__ float4         kbox[MAX_DET];     // kept set
    __shared__ float          kar[MAX_DET];
    __shared__ int            kidx[MAX_DET];
    __shared__ float4         cbox[CHUNK];       // staged chunk
    __shared__ float          car[CHUNK];
    __shared__ int            cidx[CHUNK];
    __shared__ unsigned char  ssup[CHUNK];       // suppressed by kept set
    __shared__ unsigned       validw[NW];        // validity ballots
    __shared__ unsigned       scnt[NW];          // per-warp survivor counts
    __shared__ unsigned short slist[CHUNK];      // survivor -> candidate slot
    __shared__ __align__(16) unsigned matS[CHUNK][NW];   // 8KB survivor matrix
    __shared__ int s_count, s_stop, s_m;

    const int b    = blockIdx.x;
    const int tid  = threadIdx.x;
    const int lane = tid & 31;
    const int warp = tid >> 5;
    const int nwarps = blockDim.x >> 5;

    // ---- load keys + pre-normalized boxes into smem ----
    const float4* bb4 = (const float4*)(boxes + (size_t)b * NBOX * 4);
    for (int i = tid; i < NBOX; i += blockDim.x) {
        sk[i] = keys[b * NBOX + i];
        float4 r = bb4[i];
        float y1 = fminf(r.x, r.z), y2 = fmaxf(r.x, r.z);
        float x1 = fminf(r.y, r.w), x2 = fmaxf(r.y, r.w);
        sbox[i]  = make_float4(y1, x1, y2, x2);
        sarea[i] = (y2 - y1) * (x2 - x1);
    }
    if (tid == 0) { s_count = 0; s_stop = 0; }
    __syncthreads();

    // ---- bitonic sort, descending ----
    for (int seg = warp; seg < NBOX / 32; seg += nwarps) {
        const int i = (seg << 5) + lane;
        unsigned long long v = sk[i];
        #pragma unroll
        for (int k = 2; k <= 32; k <<= 1) {
            const bool desc = ((i & k) == 0);
            #pragma unroll
            for (int j = k >> 1; j >= 1; j >>= 1) {
                unsigned long long w = __shfl_xor_sync(FULL, v, j);
                bool upper   = (i & j) != 0;
                bool takeMax = desc ^ upper;
                v = takeMax ? (v > w ? v : w) : (v < w ? v : w);
            }
        }
        sk[i] = v;
    }
    __syncthreads();

    for (int k = 64; k <= NBOX; k <<= 1) {
        for (int j = k >> 1; j >= 32; j >>= 1) {
            for (int p = tid; p < NBOX / 2; p += blockDim.x) {
                int i = ((p & ~(j - 1)) << 1) | (p & (j - 1));
                int l = i | j;
                unsigned long long a = sk[i], c = sk[l];
                bool sw = ((i & k) == 0) ? (a < c) : (a > c);
                if (sw) { sk[i] = c; sk[l] = a; }
            }
            __syncthreads();
        }
        for (int seg = warp; seg < NBOX / 32; seg += nwarps) {
            const int i = (seg << 5) + lane;
            unsigned long long v = sk[i];
            const bool desc = ((i & k) == 0);
            #pragma unroll
            for (int j = 16; j >= 1; j >>= 1) {
                unsigned long long w = __shfl_xor_sync(FULL, v, j);
                bool upper   = (i & j) != 0;
                bool takeMax = desc ^ upper;
                v = takeMax ? (v > w ? v : w) : (v < w ? v : w);
            }
            sk[i] = v;
        }
        __syncthreads();
    }

    // ---- survivor-compacted bitmap NMS ----
    for (int r = 0; r < NBOX; r += CHUNK) {
        // stage chunk (warps 0-7) + zero matrix (warps 8-31)
        if (tid < CHUNK) {
            const unsigned long long key = sk[r + tid];
            const float score = __uint_as_float((unsigned)(key >> 32));
            const int   idx = (int)(0xffffffffu - (unsigned)(key & 0xffffffffu));
            cidx[tid] = idx;
            cbox[tid] = sbox[idx];
            car[tid]  = sarea[idx];
            unsigned vb = __ballot_sync(FULL, score > CONF_THR);
            if (lane == 0) validw[warp] = vb;
        } else {
            for (int z = tid - CHUNK; z < CHUNK * NW; z += 1024 - CHUNK)
                ((unsigned*)matS)[z] = 0;
        }
        __syncthreads();

        // A1: candidates vs kept set (4 threads/candidate, fixed trip)
        {
            const int cand = tid >> 2, sub = tid & 3;
            const float4 c  = cbox[cand];
            const float  ca = car[cand];
            const int    cnt = s_count;
            bool sup = false;
            for (int j = sub; j < cnt; j += SUBS) {
                float4 kb = kbox[j];
                sup |= iou_gt(c.x, c.y, c.z, c.w, ca,
                              kb.x, kb.y, kb.z, kb.w, kar[j]);
            }
            unsigned bal = __ballot_sync(FULL, sup);
            if (sub == 0)
                ssup[cand] = ((bal >> (lane & 28)) & 0xFu) ? 1 : 0;
        }
        __syncthreads();

        // compact survivors into slist (ballot prefix, warps 0-7)
        {
            bool alive = false;
            if (tid < CHUNK)
                alive = (((validw[warp] >> lane) & 1u) != 0) && (ssup[tid] == 0);
            unsigned ab = __ballot_sync(FULL, alive);
            if (tid < CHUNK && lane == 0) scnt[warp] = __popc(ab);
            __syncthreads();
            if (tid < CHUNK && alive) {
                int off = __popc(ab & ((1u << lane) - 1u));
                #pragma unroll
                for (int w = 0; w < NW; w++)
                    if (w < warp) off += scnt[w];
                slist[off] = (unsigned short)tid;
            }
            if (tid == 0) {
                int m = 0;
                #pragma unroll
                for (int w = 0; w < NW; w++) m += scnt[w];
                s_m = m;
            }
        }
        __syncthreads();

        // A2: suppression matrix over m survivors only
        {
            const int m = s_m;
            if (m > 1) {
                const int sh = 32 - __clz(m - 1);        // ceil log2
                const int total = m << sh;
                const int bmask = (1 << sh) - 1;
                for (int idx = tid; idx < total; idx += 1024) {
                    const int a = idx >> sh;
                    const int bq = idx & bmask;
                    if (bq > a && bq < m) {
                        const int ca_ = slist[a], cb_ = slist[bq];
                        const float4 pa = cbox[ca_], pb = cbox[cb_];
                        if (iou_gt(pa.x, pa.y, pa.z, pa.w, car[ca_],
                                   pb.x, pb.y, pb.z, pb.w, car[cb_]))
                            atomicOr(&matS[a][bq >> 5], 1u << (bq & 31));
                    }
                }
            }
        }
        __syncthreads();

        // B: thread 0 resolves survivors in rank order (work ~ keeps)
        if (tid == 0) {
            const int m = s_m;
            unsigned aw[NW];
            #pragma unroll
            for (int w = 0; w < NW; w++) {
                int rem = m - w * 32;
                aw[w] = (rem >= 32) ? FULL : (rem > 0 ? ((1u << rem) - 1u) : 0u);
            }
            bool any_invalid = false;
            #pragma unroll
            for (int w = 0; w < NW; w++)
                if (validw[w] != FULL) any_invalid = true;

            int count = s_count;
            #pragma unroll
            for (int w = 0; w < NW; w++) {
                while (aw[w] && count < MAX_DET) {
                    const int bit = __ffs(aw[w]) - 1;
                    const int i = (w << 5) + bit;        // survivor index
                    aw[w] &= aw[w] - 1u;
                    const int ci = slist[i];
                    kbox[count] = cbox[ci];
                    kar[count]  = car[ci];
                    kidx[count] = cidx[ci];
                    count++;
                    #pragma unroll
                    for (int q = 0; q < NW; q++)
                        aw[q] &= ~matS[i][q];
                }
                if (count >= MAX_DET) break;
            }
            s_count = count;
            s_stop  = (count >= MAX_DET) || any_invalid;
        }
        __syncthreads();
        if (s_stop) break;
    }

    const int count = s_count;

    // ---- outputs (zero-pad beyond count) ----
    float* ob = nms_box + (size_t)b * MAX_DET * 4;
    for (int t = tid; t < MAX_DET * 4; t += blockDim.x) {
        int k = t >> 2, c = t & 3;
        ob[t] = (k < count)
              ? boxes[(size_t)b * NBOX * 4 + (size_t)kidx[k] * 4 + c]
              : 0.0f;
    }
    float* oc = nms_cls + (size_t)b * MAX_DET * NCLS;
    for (int t = tid; t < MAX_DET * NCLS; t += blockDim.x) {
        int k = t / NCLS, c = t % NCLS;
        oc[t] = (k < count)
              ? cls_soft[((size_t)b * NBOX + (size_t)kidx[k]) * NCLS + c]
              : 0.0f;
    }
}

// ---------------------------------------------------------------------------
extern "C" void kernel_launch(void* const* d_in, const int* in_sizes, int n_in,
                              void* d_out, int out_size)
{
    const float* boxes;
    const float* cls;
    if (in_sizes[0] == BATCH * NBOX * 4) {
        boxes = (const float*)d_in[0];
        cls   = (const float*)d_in[1];
    } else {
        boxes = (const float*)d_in[1];
        cls   = (const float*)d_in[0];
    }

    float* out      = (float*)d_out;
    float* nms_box  = out;                                  // [16,100,4]
    float* nms_cls  = out + BATCH * MAX_DET * 4;            // [16,100,80]
    float* cls_pred = out + BATCH * MAX_DET * 4
                          + BATCH * MAX_DET * NCLS;         // [16,4096,80]

    unsigned long long* keys = nullptr;
    cudaGetSymbolAddress((void**)&keys, g_keys);

    const int DYN_SMEM = NBOX * (int)sizeof(float4)
                       + NBOX * (int)sizeof(unsigned long long)
                       + NBOX * (int)sizeof(float);         // 112 KB
    static int smem_set = 0;
    if (!smem_set) {
        cudaFuncSetAttribute(nms_kernel,
                             cudaFuncAttributeMaxDynamicSharedMemorySize,
                             DYN_SMEM);
        smem_set = 1;
    }

    const int rows = BATCH * NBOX;
    softmax_key_kernel<<<rows / 8, 256>>>(cls, cls_pred, keys);
    nms_kernel<<<BATCH, 1024, DYN_SMEM>>>(boxes, cls_pred, keys, nms_box, nms_cls);
}

// round 9
// speedup vs baseline: 1.1643x; 1.1643x over previous
#include <cuda_runtime.h>
#include <stdint.h>

#define BATCH    16
#define NBOX     4096
#define NCLS     80
#define MAX_DET  100
#define IOU_THR  0.5f
#define CONF_THR 0.5f
#define FULL     0xffffffffu
#define CHUNK    128
#define SUBS     8                  // 1024 threads / 128 candidates
#define NW       (CHUNK / 32)       // 4 mask words
#define THREADS  1024

// scratch: per-row sort keys  (score_bits << 32) | (0xFFFFFFFF - idx)
__device__ unsigned long long g_keys[BATCH * NBOX];

// guarded IoU>0.5 test: cheap compare with exact-divide fallback in a narrow
// borderline band (validated across passing rounds).
__device__ __forceinline__ bool iou_gt(float y1a, float x1a, float y2a, float x2a, float aa,
                                       float y1b, float x1b, float y2b, float x2b, float ab)
{
    float ih = fmaxf(0.0f, fminf(y2a, y2b) - fmaxf(y1a, y1b));
    float iw = fmaxf(0.0f, fminf(x2a, x2b) - fmaxf(x1a, x1b));
    float inter = ih * iw;
    float uni   = aa + ab - inter;
    float half  = 0.5f * uni;
    float diff  = inter - half;
    if (fabsf(diff) <= half * 1e-5f) {          // borderline: exact semantics
        float iou = (inter > 0.0f) ? inter / uni : 0.0f;
        return iou > IOU_THR;
    }
    return (diff > 0.0f) && (inter > 0.0f);
}

// ---------------------------------------------------------------------------
// Kernel 1: softmax(square(x*10)) per row, write cls_predictions, emit keys.
// ---------------------------------------------------------------------------
__global__ void __launch_bounds__(256)
softmax_key_kernel(const float* __restrict__ cls_in,
                   float* __restrict__ cls_out,
                   unsigned long long* __restrict__ keys)
{
    const int lane = threadIdx.x & 31;
    const int row  = blockIdx.x * (blockDim.x >> 5) + (threadIdx.x >> 5);
    if (row >= BATCH * NBOX) return;

    const float* in = cls_in + (size_t)row * NCLS;

    const bool has2 = lane < (NCLS - 64);
    float x0 = in[lane]      * 10.0f;
    float x1 = in[lane + 32] * 10.0f;
    float x2 = has2 ? in[lane + 64] * 10.0f : 0.0f;
    float a0 = x0 * x0, a1 = x1 * x1, a2 = x2 * x2;

    float amax = fmaxf(a0, a1);
    if (has2) amax = fmaxf(amax, a2);
    #pragma unroll
    for (int o = 16; o; o >>= 1)
        amax = fmaxf(amax, __shfl_xor_sync(FULL, amax, o));

    float e0 = expf(a0 - amax);
    float e1 = expf(a1 - amax);
    float e2 = has2 ? expf(a2 - amax) : 0.0f;

    float s = e0 + e1 + e2;
    #pragma unroll
    for (int o = 16; o; o >>= 1)
        s += __shfl_xor_sync(FULL, s, o);

    const float recip = 1.0f / s;
    float o0 = e0 * recip, o1 = e1 * recip, o2 = e2 * recip;

    float* out = cls_out + (size_t)row * NCLS;
    out[lane]      = o0;
    out[lane + 32] = o1;
    if (has2) out[lane + 64] = o2;

    float m = fmaxf(o0, o1);
    if (has2) m = fmaxf(m, o2);
    #pragma unroll
    for (int o = 16; o; o >>= 1)
        m = fmaxf(m, __shfl_xor_sync(FULL, m, o));

    if (lane == 0) {
        const unsigned n = (unsigned)(row & (NBOX - 1));
        keys[row] = ((unsigned long long)__float_as_uint(m) << 32)
                  | (unsigned long long)(0xffffffffu - n);
    }
}

// ---------------------------------------------------------------------------
// Kernel 2: sort + bitmap-chunked NMS with warp-local alive-gated matrix.
//   Phase A (all threads): vs-kept check; ballot gives alive to all 8 subs
//                          -> intra-chunk matrix rows computed for ALIVE only
//   Phase B (thread 0)   : bit-scan propagation, work proportional to KEEPS
// Dynamic smem: float4 sbox[NBOX] | u64 sk[NBOX] | float sarea[NBOX]  (112KB)
// ---------------------------------------------------------------------------
__global__ void __launch_bounds__(THREADS, 1)
nms_kernel(const float* __restrict__ boxes,        // [B,N,4]
           const float* __restrict__ cls_soft,     // [B,N,C]
           const unsigned long long* __restrict__ keys,
           float* __restrict__ nms_box,            // [B,MAX_DET,4]
           float* __restrict__ nms_cls)            // [B,MAX_DET,C]
{
    extern __shared__ char dyn[];
    float4*             sbox  = (float4*)dyn;                       // 64KB
    unsigned long long* sk    = (unsigned long long*)(sbox + NBOX); // 32KB
    float*              sarea = (float*)(sk + NBOX);                // 16KB

    __shared__ float4        kbox[MAX_DET];     // kept set (all prev chunks)
    __shared__ float         kar[MAX_DET];
    __shared__ int           kidx[MAX_DET];
    __shared__ float4        cbox[CHUNK];       // staged chunk
    __shared__ float         car[CHUNK];
    __shared__ int           cidx[CHUNK];
    __shared__ unsigned char ssup[CHUNK];       // suppressed by kept set (0/1)
    __shared__ unsigned      validw[NW];        // validity ballots
    __shared__ __align__(16) unsigned short mat16[CHUNK][SUBS];  // 2KB matrix
    __shared__ int s_count, s_stop;

    const int b    = blockIdx.x;
    const int tid  = threadIdx.x;
    const int lane = tid & 31;
    const int warp = tid >> 5;

    // ---- load keys + pre-normalized boxes into smem ----
    const float4* bb4 = (const float4*)(boxes + (size_t)b * NBOX * 4);
    #pragma unroll
    for (int s = 0; s < NBOX / THREADS; s++) {
        const int i = tid + s * THREADS;
        sk[i] = keys[b * NBOX + i];
        float4 r = bb4[i];
        float y1 = fminf(r.x, r.z), y2 = fmaxf(r.x, r.z);
        float x1 = fminf(r.y, r.w), x2 = fmaxf(r.y, r.w);
        sbox[i]  = make_float4(y1, x1, y2, x2);
        sarea[i] = (y2 - y1) * (x2 - x1);
    }
    if (tid == 0) { s_count = 0; s_stop = 0; }
    __syncthreads();

    // ---- bitonic sort, descending ----
    #pragma unroll
    for (int seg = 0; seg < NBOX / 32 / 32; seg++) {     // 4 segs per warp
        const int i = ((seg * 32 + warp) << 5) + lane;
        unsigned long long v = sk[i];
        #pragma unroll
        for (int k = 2; k <= 32; k <<= 1) {
            const bool desc = ((i & k) == 0);
            #pragma unroll
            for (int j = k >> 1; j >= 1; j >>= 1) {
                unsigned long long w = __shfl_xor_sync(FULL, v, j);
                bool upper   = (i & j) != 0;
                bool takeMax = desc ^ upper;
                v = takeMax ? (v > w ? v : w) : (v < w ? v : w);
            }
        }
        sk[i] = v;
    }
    __syncthreads();

    for (int k = 64; k <= NBOX; k <<= 1) {
        for (int j = k >> 1; j >= 32; j >>= 1) {
            #pragma unroll
            for (int q = 0; q < NBOX / 2 / THREADS; q++) {
                const int p = tid + q * THREADS;
                int i = ((p & ~(j - 1)) << 1) | (p & (j - 1));
                int l = i | j;
                unsigned long long a = sk[i], c = sk[l];
                bool sw = ((i & k) == 0) ? (a < c) : (a > c);
                if (sw) { sk[i] = c; sk[l] = a; }
            }
            __syncthreads();
        }
        #pragma unroll
        for (int seg = 0; seg < NBOX / 32 / 32; seg++) {
            const int i = ((seg * 32 + warp) << 5) + lane;
            unsigned long long v = sk[i];
            const bool desc = ((i & k) == 0);
            #pragma unroll
            for (int j = 16; j >= 1; j >>= 1) {
                unsigned long long w = __shfl_xor_sync(FULL, v, j);
                bool upper   = (i & j) != 0;
                bool takeMax = desc ^ upper;
                v = takeMax ? (v > w ? v : w) : (v < w ? v : w);
            }
            sk[i] = v;
        }
        __syncthreads();
    }

    // ---- bitmap-chunked NMS ----
    for (int r = 0; r < NBOX; r += CHUNK) {
        // stage chunk: boxes, areas, indices, validity ballots
        if (tid < CHUNK) {
            const unsigned long long key = sk[r + tid];
            const float score = __uint_as_float((unsigned)(key >> 32));
            const int   idx = (int)(0xffffffffu - (unsigned)(key & 0xffffffffu));
            cidx[tid] = idx;
            cbox[tid] = sbox[idx];
            car[tid]  = sarea[idx];
            unsigned vb = __ballot_sync(FULL, score > CONF_THR);
            if (lane == 0) validw[warp] = vb;
        }
        __syncthreads();

        // Phase A: all 1024 threads; A2 gated by warp-local alive knowledge
        {
            const int cand = tid >> 3, sub = tid & 7;
            const float4 c  = cbox[cand];
            const float  ca = car[cand];

            // A1: candidate vs kept set (stride-8, fixed trip)
            const int cnt = s_count;
            bool sup = false;
            for (int j = sub; j < cnt; j += SUBS) {
                float4 kb = kbox[j];
                sup |= iou_gt(c.x, c.y, c.z, c.w, ca,
                              kb.x, kb.y, kb.z, kb.w, kar[j]);
            }
            unsigned bal = __ballot_sync(FULL, sup);
            if (sub == 0)
                ssup[cand] = ((bal >> (lane & 24)) & 0xFFu) ? 1 : 0;

            // alive = valid && not suppressed by kept set — known to all 8
            // sub-threads via the ballot, no barrier needed.
            const bool vcand = (validw[cand >> 5] >> (cand & 31)) & 1u;
            const bool alive = vcand && (((bal >> (lane & 24)) & 0xFFu) == 0u);

            // A2: matrix row bits ONLY for alive candidates (rows of
            // suppressed/invalid candidates are never read in phase B).
            if (alive) {
                unsigned bits = 0;
                const int j0 = sub << 4;
                if (j0 + 15 > cand) {
                    #pragma unroll
                    for (int t = 0; t < 16; t++) {
                        const int j = j0 + t;
                        if (j > cand) {
                            float4 d = cbox[j];
                            if (iou_gt(c.x, c.y, c.z, c.w, ca,
                                       d.x, d.y, d.z, d.w, car[j]))
                                bits |= (1u << t);
                        }
                    }
                }
                mat16[cand][sub] = (unsigned short)bits;
            }
        }
        __syncthreads();

        // Phase B: thread 0 propagates; visits kept candidates only
        if (tid == 0) {
            const unsigned* ss32 = (const unsigned*)ssup;
            unsigned aw[NW];
            bool any_invalid = false;
            #pragma unroll
            for (int w = 0; w < NW; w++) {
                unsigned v = validw[w];
                if (v != FULL) any_invalid = true;
                unsigned supb = 0;
                #pragma unroll
                for (int q = 0; q < 8; q++) {          // 4 bytes -> 4 bits
                    unsigned x = ss32[w * 8 + q];
                    unsigned nib = (x & 1u) | ((x >> 7) & 2u)
                                 | ((x >> 14) & 4u) | ((x >> 21) & 8u);
                    supb |= nib << (q * 4);
                }
                aw[w] = v & ~supb;
            }

            int count = s_count;
            #pragma unroll
            for (int w = 0; w < NW; w++) {
                while (aw[w] && count < MAX_DET) {
                    const int bit = __ffs(aw[w]) - 1;
                    const int i = (w << 5) + bit;
                    aw[w] &= aw[w] - 1;
                    // keep i
                    kbox[count] = cbox[i];
                    kar[count]  = car[i];
                    kidx[count] = cidx[i];
                    count++;
                    // suppress later candidates in this chunk
                    const uint4 row = *(const uint4*)&mat16[i][0];
                    aw[0] &= ~row.x; aw[1] &= ~row.y;
                    aw[2] &= ~row.z; aw[3] &= ~row.w;
                }
                if (count >= MAX_DET) break;
            }
            s_count = count;
            s_stop  = (count >= MAX_DET) || any_invalid;
        }
        __syncthreads();
        if (s_stop) break;
    }

    const int count = s_count;

    // ---- outputs (zero-pad beyond count) ----
    float* ob = nms_box + (size_t)b * MAX_DET * 4;
    for (int t = tid; t < MAX_DET * 4; t += THREADS) {
        int k = t >> 2, c = t & 3;
        ob[t] = (k < count)
              ? boxes[(size_t)b * NBOX * 4 + (size_t)kidx[k] * 4 + c]
              : 0.0f;
    }
    float* oc = nms_cls + (size_t)b * MAX_DET * NCLS;
    for (int t = tid; t < MAX_DET * NCLS; t += THREADS) {
        int k = t / NCLS, c = t % NCLS;
        oc[t] = (k < count)
              ? cls_soft[((size_t)b * NBOX + (size_t)kidx[k]) * NCLS + c]
              : 0.0f;
    }
}

// ---------------------------------------------------------------------------
extern "C" void kernel_launch(void* const* d_in, const int* in_sizes, int n_in,
                              void* d_out, int out_size)
{
    const float* boxes;
    const float* cls;
    if (in_sizes[0] == BATCH * NBOX * 4) {
        boxes = (const float*)d_in[0];
        cls   = (const float*)d_in[1];
    } else {
        boxes = (const float*)d_in[1];
        cls   = (const float*)d_in[0];
    }

    float* out      = (float*)d_out;
    float* nms_box  = out;                                  // [16,100,4]
    float* nms_cls  = out + BATCH * MAX_DET * 4;            // [16,100,80]
    float* cls_pred = out + BATCH * MAX_DET * 4
                          + BATCH * MAX_DET * NCLS;         // [16,4096,80]

    unsigned long long* keys = nullptr;
    cudaGetSymbolAddress((void**)&keys, g_keys);

    const int DYN_SMEM = NBOX * (int)sizeof(float4)
                       + NBOX * (int)sizeof(unsigned long long)
                       + NBOX * (int)sizeof(float);         // 112 KB
    static int smem_set = 0;
    if (!smem_set) {
        cudaFuncSetAttribute(nms_kernel,
                             cudaFuncAttributeMaxDynamicSharedMemorySize,
                             DYN_SMEM);
        smem_set = 1;
    }

    const int rows = BATCH * NBOX;
    softmax_key_kernel<<<rows / 8, 256>>>(cls, cls_pred, keys);
    nms_kernel<<<BATCH, THREADS, DYN_SMEM>>>(boxes, cls_pred, keys, nms_box, nms_cls);
}

// round 10
// speedup vs baseline: 1.2041x; 1.0342x over previous
#include <cuda_runtime.h>
#include <stdint.h>

#define BATCH    16
#define NBOX     4096
#define NCLS     80
#define MAX_DET  100
#define IOU_THR  0.5f
#define CONF_THR 0.5f
#define FULL     0xffffffffu
#define CHUNK    128
#define SUBS     8                  // 1024 threads / 128 candidates
#define NW       (CHUNK / 32)       // 4 mask words
#define THREADS  1024

// scratch: per-row sort keys  (score_bits << 32) | (0xFFFFFFFF - idx)
__device__ unsigned long long g_keys[BATCH * NBOX];

// guarded IoU>0.5 test: cheap compare with exact-divide fallback in a narrow
// borderline band (validated across passing rounds).
__device__ __forceinline__ bool iou_gt(float y1a, float x1a, float y2a, float x2a, float aa,
                                       float y1b, float x1b, float y2b, float x2b, float ab)
{
    float ih = fmaxf(0.0f, fminf(y2a, y2b) - fmaxf(y1a, y1b));
    float iw = fmaxf(0.0f, fminf(x2a, x2b) - fmaxf(x1a, x1b));
    float inter = ih * iw;
    float uni   = aa + ab - inter;
    float half  = 0.5f * uni;
    float diff  = inter - half;
    if (fabsf(diff) <= half * 1e-5f) {          // borderline: exact semantics
        float iou = (inter > 0.0f) ? inter / uni : 0.0f;
        return iou > IOU_THR;
    }
    return (diff > 0.0f) && (inter > 0.0f);
}

__device__ __forceinline__ void ce64(unsigned long long& a, unsigned long long& b, bool desc)
{
    bool sw = desc ? (a < b) : (a > b);
    if (sw) { unsigned long long t = a; a = b; b = t; }
}

__device__ __forceinline__ unsigned long long shfl_step(unsigned long long v, int j,
                                                        bool desc, int lane)
{
    unsigned long long w = __shfl_xor_sync(FULL, v, j);
    bool upper   = (lane & j) != 0;
    bool takeMax = desc ^ upper;
    return takeMax ? (v > w ? v : w) : (v < w ? v : w);
}

// ---------------------------------------------------------------------------
// Kernel 1: softmax(square(x*10)) per row, write cls_predictions, emit keys.
// ---------------------------------------------------------------------------
__global__ void __launch_bounds__(256)
softmax_key_kernel(const float* __restrict__ cls_in,
                   float* __restrict__ cls_out,
                   unsigned long long* __restrict__ keys)
{
    const int lane = threadIdx.x & 31;
    const int row  = blockIdx.x * (blockDim.x >> 5) + (threadIdx.x >> 5);
    if (row >= BATCH * NBOX) return;

    const float* in = cls_in + (size_t)row * NCLS;

    const bool has2 = lane < (NCLS - 64);
    float x0 = in[lane]      * 10.0f;
    float x1 = in[lane + 32] * 10.0f;
    float x2 = has2 ? in[lane + 64] * 10.0f : 0.0f;
    float a0 = x0 * x0, a1 = x1 * x1, a2 = x2 * x2;

    float amax = fmaxf(a0, a1);
    if (has2) amax = fmaxf(amax, a2);
    #pragma unroll
    for (int o = 16; o; o >>= 1)
        amax = fmaxf(amax, __shfl_xor_sync(FULL, amax, o));

    float e0 = expf(a0 - amax);
    float e1 = expf(a1 - amax);
    float e2 = has2 ? expf(a2 - amax) : 0.0f;

    float s = e0 + e1 + e2;
    #pragma unroll
    for (int o = 16; o; o >>= 1)
        s += __shfl_xor_sync(FULL, s, o);

    const float recip = 1.0f / s;
    float o0 = e0 * recip, o1 = e1 * recip, o2 = e2 * recip;

    float* out = cls_out + (size_t)row * NCLS;
    out[lane]      = o0;
    out[lane + 32] = o1;
    if (has2) out[lane + 64] = o2;

    float m = fmaxf(o0, o1);
    if (has2) m = fmaxf(m, o2);
    #pragma unroll
    for (int o = 16; o; o >>= 1)
        m = fmaxf(m, __shfl_xor_sync(FULL, m, o));

    if (lane == 0) {
        const unsigned n = (unsigned)(row & (NBOX - 1));
        keys[row] = ((unsigned long long)__float_as_uint(m) << 32)
                  | (unsigned long long)(0xffffffffu - n);
    }
}

// ---------------------------------------------------------------------------
// Kernel 2: register-tiled bitonic sort + double-buffered bitmap NMS.
// Dynamic smem: float4 sbox[NBOX] | u64 sk[NBOX] | float sarea[NBOX]  (112KB)
// ---------------------------------------------------------------------------
__global__ void __launch_bounds__(THREADS, 1)
nms_kernel(const float* __restrict__ boxes,        // [B,N,4]
           const float* __restrict__ cls_soft,     // [B,N,C]
           const unsigned long long* __restrict__ keys,
           float* __restrict__ nms_box,            // [B,MAX_DET,4]
           float* __restrict__ nms_cls)            // [B,MAX_DET,C]
{
    extern __shared__ char dyn[];
    float4*             sbox  = (float4*)dyn;                       // 64KB
    unsigned long long* sk    = (unsigned long long*)(sbox + NBOX); // 32KB
    float*              sarea = (float*)(sk + NBOX);                // 16KB

    __shared__ float4        kbox[MAX_DET];       // kept set
    __shared__ float         kar[MAX_DET];
    __shared__ int           kidx[MAX_DET];
    __shared__ float4        cbox[2][CHUNK];      // double-buffered chunk
    __shared__ float         car[2][CHUNK];
    __shared__ int           cidx[2][CHUNK];
    __shared__ unsigned      validw[2][NW];
    __shared__ unsigned char ssup[CHUNK];
    __shared__ __align__(16) unsigned short mat16[CHUNK][SUBS];  // 2KB matrix
    __shared__ int s_count, s_stop;

    const int b    = blockIdx.x;
    const int tid  = threadIdx.x;
    const int lane = tid & 31;
    const int warp = tid >> 5;

    // ---- load keys + pre-normalized boxes into smem ----
    const float4* bb4 = (const float4*)(boxes + (size_t)b * NBOX * 4);
    #pragma unroll
    for (int s = 0; s < NBOX / THREADS; s++) {
        const int i = tid + s * THREADS;
        sk[i] = keys[b * NBOX + i];
        float4 r = bb4[i];
        float y1 = fminf(r.x, r.z), y2 = fmaxf(r.x, r.z);
        float x1 = fminf(r.y, r.w), x2 = fmaxf(r.y, r.w);
        sbox[i]  = make_float4(y1, x1, y2, x2);
        sarea[i] = (y2 - y1) * (x2 - x1);
    }
    if (tid == 0) { s_count = 0; s_stop = 0; }
    __syncthreads();

    // ---- bitonic sort, descending ----
    // stage A: k = 2..32 fused, pure warp shuffles
    #pragma unroll
    for (int seg = 0; seg < NBOX / 32 / 32; seg++) {
        const int i = ((seg * 32 + warp) << 5) + lane;
        unsigned long long v = sk[i];
        #pragma unroll
        for (int k = 2; k <= 32; k <<= 1) {
            const bool desc = ((i & k) == 0);
            #pragma unroll
            for (int j = k >> 1; j >= 1; j >>= 1)
                v = shfl_step(v, j, desc, lane);
        }
        sk[i] = v;
    }
    __syncthreads();

    // mega-pass M1: stages k=64 and k=128 entirely in registers per 128-tile
    {
        const int base = warp << 7;
        unsigned long long r0 = sk[base + lane];
        unsigned long long r1 = sk[base + 32 + lane];
        unsigned long long r2 = sk[base + 64 + lane];
        unsigned long long r3 = sk[base + 96 + lane];
        // k = 64: pairs (r0,r1) desc, (r2,r3) asc; then j<=16 shuffles
        ce64(r0, r1, true);
        ce64(r2, r3, false);
        #pragma unroll
        for (int j = 16; j >= 1; j >>= 1) {
            r0 = shfl_step(r0, j, true,  lane);
            r1 = shfl_step(r1, j, true,  lane);
            r2 = shfl_step(r2, j, false, lane);
            r3 = shfl_step(r3, j, false, lane);
        }
        // k = 128: direction uniform per tile
        const bool d = ((warp & 1) == 0);
        ce64(r0, r2, d); ce64(r1, r3, d);    // j=64
        ce64(r0, r1, d); ce64(r2, r3, d);    // j=32
        #pragma unroll
        for (int j = 16; j >= 1; j >>= 1) {
            r0 = shfl_step(r0, j, d, lane);
            r1 = shfl_step(r1, j, d, lane);
            r2 = shfl_step(r2, j, d, lane);
            r3 = shfl_step(r3, j, d, lane);
        }
        sk[base + lane]      = r0;
        sk[base + 32 + lane] = r1;
        sk[base + 64 + lane] = r2;
        sk[base + 96 + lane] = r3;
    }
    __syncthreads();

    // stages k = 256..4096: smem passes for j>=128, then register mega-pass
    for (int k = 256; k <= NBOX; k <<= 1) {
        for (int j = k >> 1; j >= 128; j >>= 1) {
            #pragma unroll
            for (int q = 0; q < NBOX / 2 / THREADS; q++) {
                const int p = tid + q * THREADS;
                int i = ((p & ~(j - 1)) << 1) | (p & (j - 1));
                int l = i | j;
                unsigned long long a = sk[i], c = sk[l];
                bool sw = ((i & k) == 0) ? (a < c) : (a > c);
                if (sw) { sk[i] = c; sk[l] = a; }
            }
            __syncthreads();
        }
        {
            const int base = warp << 7;
            const bool d = ((base & k) == 0);
            unsigned long long r0 = sk[base + lane];
            unsigned long long r1 = sk[base + 32 + lane];
            unsigned long long r2 = sk[base + 64 + lane];
            unsigned long long r3 = sk[base + 96 + lane];
            ce64(r0, r2, d); ce64(r1, r3, d);    // j=64
            ce64(r0, r1, d); ce64(r2, r3, d);    // j=32
            #pragma unroll
            for (int j = 16; j >= 1; j >>= 1) {
                r0 = shfl_step(r0, j, d, lane);
                r1 = shfl_step(r1, j, d, lane);
                r2 = shfl_step(r2, j, d, lane);
                r3 = shfl_step(r3, j, d, lane);
            }
            sk[base + lane]      = r0;
            sk[base + 32 + lane] = r1;
            sk[base + 64 + lane] = r2;
            sk[base + 96 + lane] = r3;
        }
        __syncthreads();
    }

    // ---- prologue: stage chunk 0 into buffer 0 ----
    if (tid < CHUNK) {
        const unsigned long long key = sk[tid];
        const float score = __uint_as_float((unsigned)(key >> 32));
        const int   idx = (int)(0xffffffffu - (unsigned)(key & 0xffffffffu));
        cidx[0][tid] = idx;
        cbox[0][tid] = sbox[idx];
        car[0][tid]  = sarea[idx];
        unsigned vb = __ballot_sync(FULL, score > CONF_THR);
        if (lane == 0) validw[0][warp] = vb;
    }
    __syncthreads();

    // ---- double-buffered bitmap-chunked NMS ----
    int cur = 0;
    for (int r = 0; r < NBOX; r += CHUNK) {
        // Phase A: all threads; A2 gated by warp-local alive knowledge
        {
            const int cand = tid >> 3, sub = tid & 7;
            const float4 c  = cbox[cur][cand];
            const float  ca = car[cur][cand];
            const bool vcand = (validw[cur][cand >> 5] >> (cand & 31)) & 1u;

            const int cnt = s_count;
            bool sup = false;
            for (int j = sub; j < cnt; j += SUBS) {
                float4 kb = kbox[j];
                sup |= iou_gt(c.x, c.y, c.z, c.w, ca,
                              kb.x, kb.y, kb.z, kb.w, kar[j]);
            }
            unsigned bal = __ballot_sync(FULL, sup);
            if (sub == 0)
                ssup[cand] = ((bal >> (lane & 24)) & 0xFFu) ? 1 : 0;

            const bool alive = vcand && (((bal >> (lane & 24)) & 0xFFu) == 0u);
            if (alive) {
                unsigned bits = 0;
                const int j0 = sub << 4;
                if (j0 + 15 > cand) {
                    #pragma unroll
                    for (int t = 0; t < 16; t++) {
                        const int j = j0 + t;
                        if (j > cand) {
                            float4 d = cbox[cur][j];
                            if (iou_gt(c.x, c.y, c.z, c.w, ca,
                                       d.x, d.y, d.z, d.w, car[cur][j]))
                                bits |= (1u << t);
                        }
                    }
                }
                mat16[cand][sub] = (unsigned short)bits;
            }
        }
        __syncthreads();

        // Phase B (thread 0) + stage next chunk (warps 16-19) concurrently
        if (tid == 0) {
            const unsigned* ss32 = (const unsigned*)ssup;
            unsigned aw[NW];
            bool any_invalid = false;
            #pragma unroll
            for (int w = 0; w < NW; w++) {
                unsigned v = validw[cur][w];
                if (v != FULL) any_invalid = true;
                unsigned supb = 0;
                #pragma unroll
                for (int q = 0; q < 8; q++) {          // 4 bytes -> 4 bits
                    unsigned x = ss32[w * 8 + q];
                    unsigned nib = (x & 1u) | ((x >> 7) & 2u)
                                 | ((x >> 14) & 4u) | ((x >> 21) & 8u);
                    supb |= nib << (q * 4);
                }
                aw[w] = v & ~supb;
            }

            int count = s_count;
            #pragma unroll
            for (int w = 0; w < NW; w++) {
                while (aw[w] && count < MAX_DET) {
                    const int bit = __ffs(aw[w]) - 1;
                    const int i = (w << 5) + bit;
                    aw[w] &= aw[w] - 1;
                    kbox[count] = cbox[cur][i];
                    kar[count]  = car[cur][i];
                    kidx[count] = cidx[cur][i];
                    count++;
                    const uint4 row = *(const uint4*)&mat16[i][0];
                    aw[0] &= ~row.x; aw[1] &= ~row.y;
                    aw[2] &= ~row.z; aw[3] &= ~row.w;
                }
                if (count >= MAX_DET) break;
            }
            s_count = count;
            s_stop  = (count >= MAX_DET) || any_invalid;
        } else if (tid >= 512 && tid < 512 + CHUNK && (r + CHUNK) < NBOX) {
            const int c = tid - 512;
            const int nxt = cur ^ 1;
            const unsigned long long key = sk[r + CHUNK + c];
            const float score = __uint_as_float((unsigned)(key >> 32));
            const int   idx = (int)(0xffffffffu - (unsigned)(key & 0xffffffffu));
            cidx[nxt][c] = idx;
            cbox[nxt][c] = sbox[idx];
            car[nxt][c]  = sarea[idx];
            unsigned vb = __ballot_sync(FULL, score > CONF_THR);
            if (lane == 0) validw[nxt][c >> 5] = vb;
        }
        __syncthreads();
        if (s_stop) break;
        cur ^= 1;
    }

    const int count = s_count;

    // ---- outputs (zero-pad beyond count) ----
    float* ob = nms_box + (size_t)b * MAX_DET * 4;
    for (int t = tid; t < MAX_DET * 4; t += THREADS) {
        int k = t >> 2, c = t & 3;
        ob[t] = (k < count)
              ? boxes[(size_t)b * NBOX * 4 + (size_t)kidx[k] * 4 + c]
              : 0.0f;
    }
    float* oc = nms_cls + (size_t)b * MAX_DET * NCLS;
    for (int t = tid; t < MAX_DET * NCLS; t += THREADS) {
        int k = t / NCLS, c = t % NCLS;
        oc[t] = (k < count)
              ? cls_soft[((size_t)b * NBOX + (size_t)kidx[k]) * NCLS + c]
              : 0.0f;
    }
}

// ---------------------------------------------------------------------------
extern "C" void kernel_launch(void* const* d_in, const int* in_sizes, int n_in,
                              void* d_out, int out_size)
{
    const float* boxes;
    const float* cls;
    if (in_sizes[0] == BATCH * NBOX * 4) {
        boxes = (const float*)d_in[0];
        cls   = (const float*)d_in[1];
    } else {
        boxes = (const float*)d_in[1];
        cls   = (const float*)d_in[0];
    }

    float* out      = (float*)d_out;
    float* nms_box  = out;                                  // [16,100,4]
    float* nms_cls  = out + BATCH * MAX_DET * 4;            // [16,100,80]
    float* cls_pred = out + BATCH * MAX_DET * 4
                          + BATCH * MAX_DET * NCLS;         // [16,4096,80]

    unsigned long long* keys = nullptr;
    cudaGetSymbolAddress((void**)&keys, g_keys);

    const int DYN_SMEM = NBOX * (int)sizeof(float4)
                       + NBOX * (int)sizeof(unsigned long long)
                       + NBOX * (int)sizeof(float);         // 112 KB
    static int smem_set = 0;
    if (!smem_set) {
        cudaFuncSetAttribute(nms_kernel,
                             cudaFuncAttributeMaxDynamicSharedMemorySize,
                             DYN_SMEM);
        smem_set = 1;
    }

    const int rows = BATCH * NBOX;
    softmax_key_kernel<<<rows / 8, 256>>>(cls, cls_pred, keys);
    nms_kernel<<<BATCH, THREADS, DYN_SMEM>>>(boxes, cls_pred, keys, nms_box, nms_cls);
}

// round 11
// speedup vs baseline: 1.5158x; 1.2589x over previous
#include <cuda_runtime.h>
#include <stdint.h>

#define BATCH    16
#define NBOX     4096
#define NCLS     80
#define MAX_DET  100
#define IOU_THR  0.5f
#define CONF_THR 0.5f
#define FULL     0xffffffffu
#define CHUNK    256
#define SUBS     4                  // 1024 threads / 256 candidates
#define NW       (CHUNK / 32)       // 8 mask words
#define THREADS  1024

// scratch: per-row sort keys  (score_bits << 32) | (0xFFFFFFFF - idx)
__device__ unsigned long long g_keys[BATCH * NBOX];

// guarded IoU>0.5 test (validated across passing rounds).
__device__ __forceinline__ bool iou_gt(float y1a, float x1a, float y2a, float x2a, float aa,
                                       float y1b, float x1b, float y2b, float x2b, float ab)
{
    float ih = fmaxf(0.0f, fminf(y2a, y2b) - fmaxf(y1a, y1b));
    float iw = fmaxf(0.0f, fminf(x2a, x2b) - fmaxf(x1a, x1b));
    float inter = ih * iw;
    float uni   = aa + ab - inter;
    float half  = 0.5f * uni;
    float diff  = inter - half;
    if (fabsf(diff) <= half * 1e-5f) {          // borderline: exact semantics
        float iou = (inter > 0.0f) ? inter / uni : 0.0f;
        return iou > IOU_THR;
    }
    return (diff > 0.0f) && (inter > 0.0f);
}

__device__ __forceinline__ void ce64(unsigned long long& a, unsigned long long& b, bool desc)
{
    bool sw = desc ? (a < b) : (a > b);
    if (sw) { unsigned long long t = a; a = b; b = t; }
}

__device__ __forceinline__ unsigned long long shfl_step(unsigned long long v, int j,
                                                        bool desc, int lane)
{
    unsigned long long w = __shfl_xor_sync(FULL, v, j);
    bool upper   = (lane & j) != 0;
    bool takeMax = desc ^ upper;
    return takeMax ? (v > w ? v : w) : (v < w ? v : w);
}

// ---------------------------------------------------------------------------
// Kernel 1: softmax(square(x*10)) per row, write cls_predictions, emit keys.
// max prob == recip exactly (max exp = e^0 = 1; fp multiply monotone).
// ---------------------------------------------------------------------------
__global__ void __launch_bounds__(256)
softmax_key_kernel(const float* __restrict__ cls_in,
                   float* __restrict__ cls_out,
                   unsigned long long* __restrict__ keys)
{
    const int lane = threadIdx.x & 31;
    const int row  = blockIdx.x * (blockDim.x >> 5) + (threadIdx.x >> 5);
    if (row >= BATCH * NBOX) return;

    const float* in = cls_in + (size_t)row * NCLS;

    const bool has2 = lane < (NCLS - 64);
    float x0 = in[lane]      * 10.0f;
    float x1 = in[lane + 32] * 10.0f;
    float x2 = has2 ? in[lane + 64] * 10.0f : 0.0f;
    float a0 = x0 * x0, a1 = x1 * x1, a2 = x2 * x2;

    float amax = fmaxf(a0, a1);
    if (has2) amax = fmaxf(amax, a2);
    #pragma unroll
    for (int o = 16; o; o >>= 1)
        amax = fmaxf(amax, __shfl_xor_sync(FULL, amax, o));

    float e0 = expf(a0 - amax);
    float e1 = expf(a1 - amax);
    float e2 = has2 ? expf(a2 - amax) : 0.0f;

    float s = e0 + e1 + e2;
    #pragma unroll
    for (int o = 16; o; o >>= 1)
        s += __shfl_xor_sync(FULL, s, o);

    const float recip = 1.0f / s;

    float* out = cls_out + (size_t)row * NCLS;
    out[lane]      = e0 * recip;
    out[lane + 32] = e1 * recip;
    if (has2) out[lane + 64] = e2 * recip;

    if (lane == 0) {
        const unsigned n = (unsigned)(row & (NBOX - 1));
        keys[row] = ((unsigned long long)__float_as_uint(recip) << 32)
                  | (unsigned long long)(0xffffffffu - n);
    }
}

// ---------------------------------------------------------------------------
// Kernel 1.5: presort — sort each 1024-run of keys in smem.
// Run at offset o is descending iff (o & 1024)==0  (bitonic stage-1024 state),
// i.e. even blockIdx -> desc, odd -> asc.
// ---------------------------------------------------------------------------
__global__ void __launch_bounds__(512)
presort_kernel(unsigned long long* __restrict__ keys)
{
    __shared__ unsigned long long s[1024];
    const int tid  = threadIdx.x;
    const int lane = tid & 31;
    const bool desc_run = ((blockIdx.x & 1) == 0);
    unsigned long long* kg = keys + (size_t)blockIdx.x * 1024;

    s[tid]       = kg[tid];
    s[tid + 512] = kg[tid + 512];
    __syncthreads();

    // stages k=2..32: pure warp shuffles on both register elements
    {
        const int i0 = tid, i1 = tid + 512;
        unsigned long long v0 = s[i0], v1 = s[i1];
        #pragma unroll
        for (int k = 2; k <= 32; k <<= 1) {
            const bool d0 = ((i0 & k) == 0);
            #pragma unroll
            for (int j = k >> 1; j >= 1; j >>= 1) {
                v0 = shfl_step(v0, j, d0, lane);
                v1 = shfl_step(v1, j, d0, lane);   // low bits of i1 == i0 for k<=32
            }
        }
        s[i0] = v0; s[i1] = v1;
    }
    __syncthreads();

    // stages k=64..1024: smem passes for j>=32, shfl pass for j<=16.
    // final stage (k=1024) direction forced to desc_run.
    for (int k = 64; k <= 1024; k <<= 1) {
        for (int j = k >> 1; j >= 32; j >>= 1) {
            const int p = tid;
            const int i = ((p & ~(j - 1)) << 1) | (p & (j - 1));
            const int l = i | j;
            const bool d = (k == 1024) ? desc_run : ((i & k) == 0);
            unsigned long long a = s[i], c = s[l];
            bool sw = d ? (a < c) : (a > c);
            if (sw) { s[i] = c; s[l] = a; }
            __syncthreads();
        }
        {
            const int i0 = tid, i1 = tid + 512;
            unsigned long long v0 = s[i0], v1 = s[i1];
            const bool d0 = (k == 1024) ? desc_run : ((i0 & k) == 0);
            const bool d1 = (k == 1024) ? desc_run : ((i1 & k) == 0);
            #pragma unroll
            for (int j = 16; j >= 1; j >>= 1) {
                v0 = shfl_step(v0, j, d0, lane);
                v1 = shfl_step(v1, j, d1, lane);
            }
            s[i0] = v0; s[i1] = v1;
        }
        __syncthreads();
    }

    kg[tid]       = s[tid];
    kg[tid + 512] = s[tid + 512];
}

// ---------------------------------------------------------------------------
// Kernel 2: finish sort (k=2048,4096) + double-buffered bitmap NMS, CHUNK=256.
// Dynamic smem: float4 sbox[NBOX] | u64 sk[NBOX] | float sarea[NBOX]  (112KB)
// ---------------------------------------------------------------------------
__global__ void __launch_bounds__(THREADS, 1)
nms_kernel(const float* __restrict__ boxes,        // [B,N,4]
           const float* __restrict__ cls_soft,     // [B,N,C]
           const unsigned long long* __restrict__ keys,
           float* __restrict__ nms_box,            // [B,MAX_DET,4]
           float* __restrict__ nms_cls)            // [B,MAX_DET,C]
{
    extern __shared__ char dyn[];
    float4*             sbox  = (float4*)dyn;                       // 64KB
    unsigned long long* sk    = (unsigned long long*)(sbox + NBOX); // 32KB
    float*              sarea = (float*)(sk + NBOX);                // 16KB

    __shared__ float4        kbox[MAX_DET];       // kept set
    __shared__ float         kar[MAX_DET];
    __shared__ int           kidx[MAX_DET];
    __shared__ float4        cbox[2][CHUNK];      // double-buffered chunk
    __shared__ float         car[2][CHUNK];
    __shared__ int           cidx[2][CHUNK];
    __shared__ unsigned      validw[2][NW];
    __shared__ unsigned char ssup[CHUNK];
    __shared__ __align__(16) unsigned mat32[CHUNK][NW];   // 8KB matrix
    __shared__ int s_count, s_stop;

    const int b    = blockIdx.x;
    const int tid  = threadIdx.x;
    const int lane = tid & 31;
    const int warp = tid >> 5;

    // ---- load keys (pre-sorted 1024-runs) + pre-normalized boxes ----
    const float4* bb4 = (const float4*)(boxes + (size_t)b * NBOX * 4);
    #pragma unroll
    for (int s = 0; s < NBOX / THREADS; s++) {
        const int i = tid + s * THREADS;
        sk[i] = keys[b * NBOX + i];
        float4 r = bb4[i];
        float y1 = fminf(r.x, r.z), y2 = fmaxf(r.x, r.z);
        float x1 = fminf(r.y, r.w), x2 = fmaxf(r.y, r.w);
        sbox[i]  = make_float4(y1, x1, y2, x2);
        sarea[i] = (y2 - y1) * (x2 - x1);
    }
    if (tid == 0) { s_count = 0; s_stop = 0; }
    __syncthreads();

    // ---- bitonic stages k = 2048, 4096 (runs of 1024 already sorted) ----
    for (int k = 2048; k <= NBOX; k <<= 1) {
        for (int j = k >> 1; j >= 128; j >>= 1) {
            #pragma unroll
            for (int q = 0; q < NBOX / 2 / THREADS; q++) {
                const int p = tid + q * THREADS;
                int i = ((p & ~(j - 1)) << 1) | (p & (j - 1));
                int l = i | j;
                unsigned long long a = sk[i], c = sk[l];
                bool sw = ((i & k) == 0) ? (a < c) : (a > c);
                if (sw) { sk[i] = c; sk[l] = a; }
            }
            __syncthreads();
        }
        {   // register mega-pass: j = 64, 32, <=16
            const int base = warp << 7;
            const bool d = ((base & k) == 0);
            unsigned long long r0 = sk[base + lane];
            unsigned long long r1 = sk[base + 32 + lane];
            unsigned long long r2 = sk[base + 64 + lane];
            unsigned long long r3 = sk[base + 96 + lane];
            ce64(r0, r2, d); ce64(r1, r3, d);    // j=64
            ce64(r0, r1, d); ce64(r2, r3, d);    // j=32
            #pragma unroll
            for (int j = 16; j >= 1; j >>= 1) {
                r0 = shfl_step(r0, j, d, lane);
                r1 = shfl_step(r1, j, d, lane);
                r2 = shfl_step(r2, j, d, lane);
                r3 = shfl_step(r3, j, d, lane);
            }
            sk[base + lane]      = r0;
            sk[base + 32 + lane] = r1;
            sk[base + 64 + lane] = r2;
            sk[base + 96 + lane] = r3;
        }
        __syncthreads();
    }

    // ---- prologue: stage chunk 0 into buffer 0 ----
    if (tid < CHUNK) {
        const unsigned long long key = sk[tid];
        const float score = __uint_as_float((unsigned)(key >> 32));
        const int   idx = (int)(0xffffffffu - (unsigned)(key & 0xffffffffu));
        cidx[0][tid] = idx;
        cbox[0][tid] = sbox[idx];
        car[0][tid]  = sarea[idx];
        unsigned vb = __ballot_sync(FULL, score > CONF_THR);
        if (lane == 0) validw[0][warp] = vb;
    }
    __syncthreads();

    // ---- double-buffered bitmap-chunked NMS ----
    int cur = 0;
    for (int r = 0; r < NBOX; r += CHUNK) {
        // Phase A: all threads; matrix gated by warp-local alive knowledge
        {
            const int cand = tid >> 2, sub = tid & 3;
            const float4 c  = cbox[cur][cand];
            const float  ca = car[cur][cand];
            const bool vcand = (validw[cur][cand >> 5] >> (cand & 31)) & 1u;

            // A1: candidate vs kept set (stride-4, fixed trip)
            const int cnt = s_count;
            bool sup = false;
            for (int j = sub; j < cnt; j += SUBS) {
                float4 kb = kbox[j];
                sup |= iou_gt(c.x, c.y, c.z, c.w, ca,
                              kb.x, kb.y, kb.z, kb.w, kar[j]);
            }
            unsigned bal = __ballot_sync(FULL, sup);
            if (sub == 0)
                ssup[cand] = ((bal >> (lane & 28)) & 0xFu) ? 1 : 0;

            const bool alive = vcand && (((bal >> (lane & 28)) & 0xFu) == 0u);

            // A2: matrix row words (64 bits per sub) only for alive rows
            if (alive) {
                unsigned bits0 = 0, bits1 = 0;
                const int j0 = sub << 6;
                if (j0 + 31 > cand) {
                    #pragma unroll
                    for (int t = 0; t < 32; t++) {
                        const int j = j0 + t;
                        if (j > cand) {
                            float4 d = cbox[cur][j];
                            if (iou_gt(c.x, c.y, c.z, c.w, ca,
                                       d.x, d.y, d.z, d.w, car[cur][j]))
                                bits0 |= (1u << t);
                        }
                    }
                }
                if (j0 + 63 > cand) {
                    #pragma unroll
                    for (int t = 0; t < 32; t++) {
                        const int j = j0 + 32 + t;
                        if (j > cand) {
                            float4 d = cbox[cur][j];
                            if (iou_gt(c.x, c.y, c.z, c.w, ca,
                                       d.x, d.y, d.z, d.w, car[cur][j]))
                                bits1 |= (1u << t);
                        }
                    }
                }
                mat32[cand][2 * sub]     = bits0;
                mat32[cand][2 * sub + 1] = bits1;
            }
        }
        __syncthreads();

        // Phase B (thread 0) + stage next chunk (warps 16-23) concurrently
        if (tid == 0) {
            const unsigned* ss32 = (const unsigned*)ssup;
            unsigned aw[NW];
            bool any_invalid = false;
            #pragma unroll
            for (int w = 0; w < NW; w++) {
                unsigned v = validw[cur][w];
                if (v != FULL) any_invalid = true;
                unsigned supb = 0;
                #pragma unroll
                for (int q = 0; q < 8; q++) {          // 4 bytes -> 4 bits
                    unsigned x = ss32[w * 8 + q];
                    unsigned nib = (x & 1u) | ((x >> 7) & 2u)
                                 | ((x >> 14) & 4u) | ((x >> 21) & 8u);
                    supb |= nib << (q * 4);
                }
                aw[w] = v & ~supb;
            }

            int count = s_count;
            #pragma unroll
            for (int w = 0; w < NW; w++) {
                while (aw[w] && count < MAX_DET) {
                    const int bit = __ffs(aw[w]) - 1;
                    const int i = (w << 5) + bit;
                    aw[w] &= aw[w] - 1;
                    kbox[count] = cbox[cur][i];
                    kar[count]  = car[cur][i];
                    kidx[count] = cidx[cur][i];
                    count++;
                    const uint4 ra = *(const uint4*)&mat32[i][0];
                    const uint4 rb = *(const uint4*)&mat32[i][4];
                    aw[0] &= ~ra.x; aw[1] &= ~ra.y; aw[2] &= ~ra.z; aw[3] &= ~ra.w;
                    aw[4] &= ~rb.x; aw[5] &= ~rb.y; aw[6] &= ~rb.z; aw[7] &= ~rb.w;
                }
                if (count >= MAX_DET) break;
            }
            s_count = count;
            s_stop  = (count >= MAX_DET) || any_invalid;
        } else if (tid >= 512 && tid < 512 + CHUNK && (r + CHUNK) < NBOX) {
            const int c = tid - 512;
            const int nxt = cur ^ 1;
            const unsigned long long key = sk[r + CHUNK + c];
            const float score = __uint_as_float((unsigned)(key >> 32));
            const int   idx = (int)(0xffffffffu - (unsigned)(key & 0xffffffffu));
            cidx[nxt][c] = idx;
            cbox[nxt][c] = sbox[idx];
            car[nxt][c]  = sarea[idx];
            unsigned vb = __ballot_sync(FULL, score > CONF_THR);
            if (lane == 0) validw[nxt][c >> 5] = vb;
        }
        __syncthreads();
        if (s_stop) break;
        cur ^= 1;
    }

    const int count = s_count;

    // ---- outputs (zero-pad beyond count), vectorized ----
    float4* ob4 = (float4*)(nms_box + (size_t)b * MAX_DET * 4);
    for (int t = tid; t < MAX_DET; t += THREADS)
        ob4[t] = (t < count) ? bb4[kidx[t]] : make_float4(0.f, 0.f, 0.f, 0.f);

    float4* oc4 = (float4*)(nms_cls + (size_t)b * MAX_DET * NCLS);
    const float4* cs4 = (const float4*)cls_soft;
    for (int t = tid; t < MAX_DET * (NCLS / 4); t += THREADS) {
        int k = t / (NCLS / 4), c = t % (NCLS / 4);
        oc4[t] = (k < count)
               ? cs4[((size_t)b * NBOX + (size_t)kidx[k]) * (NCLS / 4) + c]
               : make_float4(0.f, 0.f, 0.f, 0.f);
    }
}

// ---------------------------------------------------------------------------
extern "C" void kernel_launch(void* const* d_in, const int* in_sizes, int n_in,
                              void* d_out, int out_size)
{
    const float* boxes;
    const float* cls;
    if (in_sizes[0] == BATCH * NBOX * 4) {
        boxes = (const float*)d_in[0];
        cls   = (const float*)d_in[1];
    } else {
        boxes = (const float*)d_in[1];
        cls   = (const float*)d_in[0];
    }

    float* out      = (float*)d_out;
    float* nms_box  = out;                                  // [16,100,4]
    float* nms_cls  = out + BATCH * MAX_DET * 4;            // [16,100,80]
    float* cls_pred = out + BATCH * MAX_DET * 4
                          + BATCH * MAX_DET * NCLS;         // [16,4096,80]

    unsigned long long* keys = nullptr;
    cudaGetSymbolAddress((void**)&keys, g_keys);

    const int DYN_SMEM = NBOX * (int)sizeof(float4)
                       + NBOX * (int)sizeof(unsigned long long)
                       + NBOX * (int)sizeof(float);         // 112 KB
    static int smem_set = 0;
    if (!smem_set) {
        cudaFuncSetAttribute(nms_kernel,
                             cudaFuncAttributeMaxDynamicSharedMemorySize,
                             DYN_SMEM);
        smem_set = 1;
    }

    const int rows = BATCH * NBOX;
    softmax_key_kernel<<<rows / 8, 256>>>(cls, cls_pred, keys);
    presort_kernel<<<BATCH * 4, 512>>>(keys);
    nms_kernel<<<BATCH, THREADS, DYN_SMEM>>>(boxes, cls_pred, keys, nms_box, nms_cls);
}